// round 9
// baseline (speedup 1.0000x reference)
#include <cuda_runtime.h>
#include <cstdint>

// Problem constants (fixed shape (8,2048,2048) fp32, ratio 0.1)
#define N_ELEMS   33554432
#define N_VEC4    (N_ELEMS / 4)
#define K_TOP     3355443           // int(0.1 * N)
#define SBINS     8192              // sample histogram bins (top 13 bits of 31-bit key)
#define SSHIFT    18
#define WIN_BINS  (1 << 20)         // window: 4 coarse sample bins = 2^20 key values
#define NBUCK     4096              // in-window buckets of 256 key values each
#define EQ_CAP    65536
#define LIST_CAP  (1 << 21)         // 2M staged i4 indices (expected ~830K)
#define STAGE_CAP 2048              // per-block staging (mean ~810)
#define SAMPLE_V4 262144            // 1/32 of float4s sampled
#define STARGET   (K_TOP / 32)

#define GRID_PREP 128
#define BLK_PREP  256
#define GRID_MAIN 1024              // 1024*256 threads; N_VEC4/(2*stride)=16 exact
#define BLK_MAIN  256
#define GRID_TAIL 256
#define BLK_TAIL  256

__device__ unsigned int g_shist[SBINS];
__device__ unsigned int g_hA[NBUCK];
__device__ unsigned int g_above;
__device__ unsigned int g_lo;
__device__ unsigned int g_nList;
__device__ unsigned int g_i4List[LIST_CAP];
__device__ unsigned int g_eqCount;
__device__ uint2        g_eq[EQ_CAP];
// barrier counters. g_pbar*/g_pexit are reset by k_prep itself at exit
// (last-exiter), so they are 0 at every entry. g_tbar* are zeroed by k_prep.
__device__ unsigned int g_pbar0, g_pbar1, g_pexit;
__device__ unsigned int g_tbar0, g_tbar1;

// Software grid barrier: valid because every grid here is far below the
// chip's co-residency capacity. fence-release on arrive; spin on counter.
__device__ __forceinline__ void grid_bar(unsigned int* ctr, unsigned target) {
    __syncthreads();
    if (threadIdx.x == 0) {
        __threadfence();
        atomicAdd(ctr, 1u);
        while (*(volatile unsigned int*)ctr < target) __nanosleep(64);
    }
    __syncthreads();
}

// ---------------------------------------------------------------------------
// Kernel 1: zero scratch -> sample 1/32 into 13-bit histogram -> locate the
// coarse bin of the k-th value -> publish window base g_lo.
__global__ void __launch_bounds__(BLK_PREP) k_prep(const float4* __restrict__ x) {
    __shared__ unsigned int sh[SBINS];
    __shared__ unsigned int scan[BLK_PREP];

    const int tid = blockIdx.x * blockDim.x + threadIdx.x;
    const int nthreads = GRID_PREP * BLK_PREP;

    // phase 0: zero all global scratch used later this replay
    for (int i = tid; i < SBINS; i += nthreads) g_shist[i] = 0;
    for (int i = tid; i < NBUCK; i += nthreads) g_hA[i] = 0;
    if (tid == 0) {
        g_above = 0; g_nList = 0; g_eqCount = 0;
        g_tbar0 = 0; g_tbar1 = 0;
    }
    grid_bar(&g_pbar0, GRID_PREP);

    // phase 1: sample into shared histogram, flush
    for (int i = threadIdx.x; i < SBINS; i += BLK_PREP) sh[i] = 0;
    __syncthreads();
    for (int i = tid; i < SAMPLE_V4; i += nthreads) {
        int p = ((i >> 6) << 11) + (i & 63);   // 64 f4 per 2048-f4 group
        float4 v = x[p];
        atomicAdd(&sh[(__float_as_uint(v.x) & 0x7FFFFFFFu) >> SSHIFT], 1u);
        atomicAdd(&sh[(__float_as_uint(v.y) & 0x7FFFFFFFu) >> SSHIFT], 1u);
        atomicAdd(&sh[(__float_as_uint(v.z) & 0x7FFFFFFFu) >> SSHIFT], 1u);
        atomicAdd(&sh[(__float_as_uint(v.w) & 0x7FFFFFFFu) >> SSHIFT], 1u);
    }
    __syncthreads();
    for (int i = threadIdx.x; i < SBINS; i += BLK_PREP) {
        unsigned c = sh[i];
        if (c) atomicAdd(&g_shist[i], c);
    }
    grid_bar(&g_pbar1, GRID_PREP);

    // phase 2: block 0 scans the sample histogram from the top
    if (blockIdx.x == 0) {
        int t = threadIdx.x;
        unsigned s = 0;
#pragma unroll
        for (int j = 0; j < SBINS / BLK_PREP; j++) s += g_shist[t * (SBINS / BLK_PREP) + j];
        scan[t] = s;
        __syncthreads();
        for (int d = 1; d < BLK_PREP; d <<= 1) {
            unsigned v = (t + d < BLK_PREP) ? scan[t + d] : 0;
            __syncthreads();
            scan[t] += v;
            __syncthreads();
        }
        unsigned segAbove = (t < BLK_PREP - 1) ? scan[t + 1] : 0;
        if (scan[t] >= (unsigned)STARGET && segAbove < (unsigned)STARGET) {
            unsigned acc = segAbove;
            int bin = t * (SBINS / BLK_PREP);
            for (int j = SBINS / BLK_PREP - 1; j >= 0; j--) {
                acc += g_shist[t * (SBINS / BLK_PREP) + j];
                if (acc >= (unsigned)STARGET) { bin = t * (SBINS / BLK_PREP) + j; break; }
            }
            int lo_bin = bin >= 2 ? bin - 2 : 0;
            if (lo_bin > SBINS - 4) lo_bin = SBINS - 4;
            g_lo = (unsigned)lo_bin << SSHIFT;
        }
        __syncthreads();
    }

    // exit-reset of this kernel's own barrier counters (safe: every block has
    // passed both spins before its exit-add; last exiter sees all arrived)
    __syncthreads();
    if (threadIdx.x == 0) {
        unsigned r = atomicAdd(&g_pexit, 1u);
        if (r == GRID_PREP - 1) {
            g_pbar0 = 0; g_pbar1 = 0; g_pexit = 0;
            __threadfence();
        }
    }
}

// ---------------------------------------------------------------------------
// Kernel 2: FUSED streaming pass (lean R6 body, unroll x2 with hoisted loads):
// read x, write provisional out (keep iff b>=hi), count 'above', stage i4 of
// any window-touching float4 via one ballot per f4.
__global__ void __launch_bounds__(BLK_MAIN) k_main(const float4* __restrict__ x,
                                                   float4* __restrict__ out) {
    __shared__ unsigned s_stage[STAGE_CAP];
    __shared__ unsigned s_count, s_above, s_base;

    if (threadIdx.x == 0) { s_count = 0; s_above = 0; }
    __syncthreads();

    const unsigned lo = g_lo;
    const unsigned hi = lo + WIN_BINS;
    const unsigned lane = threadIdx.x & 31u;
    const unsigned stride = GRID_MAIN * BLK_MAIN;
    unsigned above = 0;

    unsigned i = blockIdx.x * blockDim.x + threadIdx.x;
    for (int it = 0; it < N_VEC4 / (2 * GRID_MAIN * BLK_MAIN); it++) {
        float4 v0 = x[i];
        float4 v1 = x[i + stride];

        {
            unsigned b0 = __float_as_uint(v0.x) & 0x7FFFFFFFu;
            unsigned b1 = __float_as_uint(v0.y) & 0x7FFFFFFFu;
            unsigned b2 = __float_as_uint(v0.z) & 0x7FFFFFFFu;
            unsigned b3 = __float_as_uint(v0.w) & 0x7FFFFFFFu;
            float4 o;
            o.x = (b0 >= hi) ? v0.x : 0.0f;
            o.y = (b1 >= hi) ? v0.y : 0.0f;
            o.z = (b2 >= hi) ? v0.z : 0.0f;
            o.w = (b3 >= hi) ? v0.w : 0.0f;
            out[i] = o;
            above += (b0 >= hi) + (b1 >= hi) + (b2 >= hi) + (b3 >= hi);
            bool win = ((b0 - lo) < WIN_BINS) | ((b1 - lo) < WIN_BINS) |
                       ((b2 - lo) < WIN_BINS) | ((b3 - lo) < WIN_BINS);
            unsigned m = __ballot_sync(0xFFFFFFFFu, win);
            if (m) {
                int leader = __ffs(m) - 1;
                unsigned base;
                if ((int)lane == leader)
                    base = atomicAdd(&s_count, (unsigned)__popc(m));
                base = __shfl_sync(0xFFFFFFFFu, base, leader);
                if (win) {
                    unsigned pos = base + __popc(m & ((1u << lane) - 1u));
                    if (pos < STAGE_CAP) s_stage[pos] = i;
                }
            }
        }
        {
            unsigned j = i + stride;
            unsigned b0 = __float_as_uint(v1.x) & 0x7FFFFFFFu;
            unsigned b1 = __float_as_uint(v1.y) & 0x7FFFFFFFu;
            unsigned b2 = __float_as_uint(v1.z) & 0x7FFFFFFFu;
            unsigned b3 = __float_as_uint(v1.w) & 0x7FFFFFFFu;
            float4 o;
            o.x = (b0 >= hi) ? v1.x : 0.0f;
            o.y = (b1 >= hi) ? v1.y : 0.0f;
            o.z = (b2 >= hi) ? v1.z : 0.0f;
            o.w = (b3 >= hi) ? v1.w : 0.0f;
            out[j] = o;
            above += (b0 >= hi) + (b1 >= hi) + (b2 >= hi) + (b3 >= hi);
            bool win = ((b0 - lo) < WIN_BINS) | ((b1 - lo) < WIN_BINS) |
                       ((b2 - lo) < WIN_BINS) | ((b3 - lo) < WIN_BINS);
            unsigned m = __ballot_sync(0xFFFFFFFFu, win);
            if (m) {
                int leader = __ffs(m) - 1;
                unsigned base;
                if ((int)lane == leader)
                    base = atomicAdd(&s_count, (unsigned)__popc(m));
                base = __shfl_sync(0xFFFFFFFFu, base, leader);
                if (win) {
                    unsigned pos = base + __popc(m & ((1u << lane) - 1u));
                    if (pos < STAGE_CAP) s_stage[pos] = j;
                }
            }
        }
        i += 2 * stride;
    }

#pragma unroll
    for (int off = 16; off; off >>= 1) above += __shfl_down_sync(0xFFFFFFFFu, above, off);
    if (lane == 0 && above) atomicAdd(&s_above, above);
    __syncthreads();

    if (threadIdx.x == 0) {
        if (s_above) atomicAdd(&g_above, s_above);
        unsigned n = s_count < STAGE_CAP ? s_count : STAGE_CAP;
        s_base = atomicAdd(&g_nList, n);
        s_count = n;
    }
    __syncthreads();
    unsigned n = s_count, base = s_base;
    for (unsigned j = threadIdx.x; j < n; j += BLK_MAIN) {
        unsigned pos = base + j;
        if (pos < LIST_CAP) g_i4List[pos] = s_stage[j];
    }
}

// ---------------------------------------------------------------------------
// Kernel 3: tail. Phase A: gather staged f4s, build 4096-bucket histogram.
// Grid barrier. Phase B: every block redundantly scans the histogram
// (deterministic c*, need), re-gathers its slice, writes sure keepers and
// collects winning-bucket elements. Grid barrier. Block 0 does the exact
// selection by (|value| desc, index asc) — lax.top_k stable order.
__global__ void __launch_bounds__(BLK_TAIL) k_tail(const float4* __restrict__ x,
                                                   float* __restrict__ out) {
    __shared__ unsigned s_hist[NBUCK];
    __shared__ unsigned scan[BLK_TAIL];
    __shared__ int s_c;
    __shared__ unsigned s_need;

    const unsigned lo = g_lo;
    unsigned n = g_nList; if (n > LIST_CAP) n = LIST_CAP;
    const unsigned gstride = GRID_TAIL * BLK_TAIL;

    // phase A: bucket histogram from gathered staged entries
    for (int j = threadIdx.x; j < NBUCK; j += BLK_TAIL) s_hist[j] = 0;
    __syncthreads();
    for (unsigned j = blockIdx.x * blockDim.x + threadIdx.x; j < n; j += gstride) {
        float4 v = x[g_i4List[j]];
        unsigned b;
        b = (__float_as_uint(v.x) & 0x7FFFFFFFu) - lo;
        if (b < WIN_BINS) atomicAdd(&s_hist[b >> 8], 1u);
        b = (__float_as_uint(v.y) & 0x7FFFFFFFu) - lo;
        if (b < WIN_BINS) atomicAdd(&s_hist[b >> 8], 1u);
        b = (__float_as_uint(v.z) & 0x7FFFFFFFu) - lo;
        if (b < WIN_BINS) atomicAdd(&s_hist[b >> 8], 1u);
        b = (__float_as_uint(v.w) & 0x7FFFFFFFu) - lo;
        if (b < WIN_BINS) atomicAdd(&s_hist[b >> 8], 1u);
    }
    __syncthreads();
    for (int j = threadIdx.x; j < NBUCK; j += BLK_TAIL) {
        unsigned c = s_hist[j];
        if (c) atomicAdd(&g_hA[j], c);
    }
    grid_bar(&g_tbar0, GRID_TAIL);

    // phase B: redundant deterministic scan of g_hA in every block
    {
        int t = threadIdx.x;
        unsigned s = 0;
#pragma unroll
        for (int j = 0; j < NBUCK / BLK_TAIL; j++) s += g_hA[t * (NBUCK / BLK_TAIL) + j];
        scan[t] = s;
        __syncthreads();
        for (int d = 1; d < BLK_TAIL; d <<= 1) {
            unsigned v = (t + d < BLK_TAIL) ? scan[t + d] : 0;
            __syncthreads();
            scan[t] += v;
            __syncthreads();
        }
        long long kRem = (long long)K_TOP - (long long)g_above;
        unsigned winTotal = scan[0];
        if (t == 0) { s_c = 0x7FFFFFFF; s_need = 0; }   // default: none from window
        __syncthreads();
        if (kRem >= 1 && kRem <= (long long)winTotal) {
            unsigned segAbove = (t < BLK_TAIL - 1) ? scan[t + 1] : 0;
            if ((long long)scan[t] >= kRem && (long long)segAbove < kRem) {
                unsigned acc = segAbove;
                for (int j = NBUCK / BLK_TAIL - 1; j >= 0; j--) {
                    unsigned h = g_hA[t * (NBUCK / BLK_TAIL) + j];
                    if ((long long)(acc + h) >= kRem) {
                        s_c = t * (NBUCK / BLK_TAIL) + j;
                        s_need = (unsigned)(kRem - (long long)acc);
                        break;
                    }
                    acc += h;
                }
            }
        } else if (kRem > (long long)winTotal) {
            if (t == 0) { s_c = -1; s_need = 0; }       // keep entire window
        }
        __syncthreads();
    }
    const int cstar = s_c;
    const unsigned need = s_need;

    // re-gather slice: write sure keepers, collect winning-bucket elements
    for (unsigned j = blockIdx.x * blockDim.x + threadIdx.x; j < n; j += gstride) {
        unsigned i4 = g_i4List[j];
        float4 v = x[i4];
        unsigned raw[4] = { __float_as_uint(v.x), __float_as_uint(v.y),
                            __float_as_uint(v.z), __float_as_uint(v.w) };
#pragma unroll
        for (int c = 0; c < 4; c++) {
            unsigned b = raw[c] & 0x7FFFFFFFu;
            if ((b - lo) < WIN_BINS) {
                int bucket = (int)((b - lo) >> 8);
                if (bucket > cstar) {
                    out[i4 * 4u + c] = __uint_as_float(raw[c]);
                } else if (bucket == cstar) {
                    unsigned p = atomicAdd(&g_eqCount, 1u);
                    if (p < EQ_CAP) g_eq[p] = make_uint2(i4 * 4u + c, raw[c]);
                }
            }
        }
    }
    grid_bar(&g_tbar1, GRID_TAIL);

    // block 0: exact in-bucket selection
    if (blockIdx.x == 0 && need > 0) {
        unsigned cnt = *(volatile unsigned*)&g_eqCount;
        if (cnt > EQ_CAP) cnt = EQ_CAP;
        for (unsigned i = threadIdx.x; i < cnt; i += BLK_TAIL) {
            uint2 ei = g_eq[i];
            unsigned bi = ei.y & 0x7FFFFFFFu;
            unsigned rank = 0;
            for (unsigned j2 = 0; j2 < cnt; j2++) {
                uint2 ej = g_eq[j2];
                unsigned bj = ej.y & 0x7FFFFFFFu;
                rank += (bj > bi) || (bj == bi && ej.x < ei.x);
            }
            if (rank < need) out[ei.x] = __uint_as_float(ei.y);
        }
    }
}

// ---------------------------------------------------------------------------
extern "C" void kernel_launch(void* const* d_in, const int* in_sizes, int n_in,
                              void* d_out, int out_size) {
    const float* x = (const float*)d_in[0];
    float* out = (float*)d_out;

    k_prep<<<GRID_PREP, BLK_PREP>>>((const float4*)x);
    k_main<<<GRID_MAIN, BLK_MAIN>>>((const float4*)x, (float4*)out);
    k_tail<<<GRID_TAIL, BLK_TAIL>>>((const float4*)x, out);
}

// round 10
// speedup vs baseline: 1.1197x; 1.1197x over previous
#include <cuda_runtime.h>
#include <cstdint>

// Problem constants (fixed shape (8,2048,2048) fp32, ratio 0.1)
#define N_ELEMS   33554432
#define N_VEC4    (N_ELEMS / 4)
#define K_TOP     3355443           // int(0.1 * N)
#define SBINS     8192              // sample histogram bins (top 13 bits of 31-bit key)
#define SSHIFT    18
#define WIN_BINS  (1 << 20)         // exact window: 4 coarse bins = 2^20 key values
#define WCHUNK    1024
#define NCHUNKS   (WIN_BINS / WCHUNK)
#define EQ_CAP    65536
#define LIST_CAP  (1 << 21)         // 2M staged i4 indices (expected ~830K)
#define STAGE_CAP 2048              // per-block staging (mean ~810)
#define SAMPLE_V4 262144            // 1/32 of float4s sampled
#define STARGET   (K_TOP / 32)

#define GRID_MAIN 1024              // 1024*256 = 262144 threads; N_VEC4 divisible
#define BLK_MAIN  256

__device__ unsigned int g_shist[SBINS];
__device__ unsigned int g_winHist[WIN_BINS];
__device__ unsigned int g_chunkSum[NCHUNKS];
__device__ unsigned int g_above;
__device__ unsigned int g_lo;
__device__ unsigned int g_T;
__device__ unsigned int g_need;
__device__ unsigned int g_nList;
__device__ unsigned int g_i4List[LIST_CAP];
__device__ unsigned int g_eqCount;
__device__ uint2        g_eq[EQ_CAP];

// ---------------------------------------------------------------------------
__global__ void k_zero() {
    int tid = blockIdx.x * blockDim.x + threadIdx.x;
    int stride = gridDim.x * blockDim.x;
    for (int i = tid; i < WIN_BINS; i += stride) g_winHist[i] = 0;
    for (int i = tid; i < SBINS; i += stride) g_shist[i] = 0;
    if (tid == 0) { g_above = 0; g_eqCount = 0; g_nList = 0; }
}

// ---------------------------------------------------------------------------
// Sample 1/32 of the data into a 13-bit shared histogram, flush to global.
__global__ void k_sample(const float4* __restrict__ x) {
    __shared__ unsigned int sh[SBINS];
    for (int i = threadIdx.x; i < SBINS; i += blockDim.x) sh[i] = 0;
    __syncthreads();

    int tid = blockIdx.x * blockDim.x + threadIdx.x;
    int stride = gridDim.x * blockDim.x;
    for (int i = tid; i < SAMPLE_V4; i += stride) {
        int p = ((i >> 6) << 11) + (i & 63);   // 64 f4 per 2048-f4 group
        float4 v = x[p];
        atomicAdd(&sh[(__float_as_uint(v.x) & 0x7FFFFFFFu) >> SSHIFT], 1u);
        atomicAdd(&sh[(__float_as_uint(v.y) & 0x7FFFFFFFu) >> SSHIFT], 1u);
        atomicAdd(&sh[(__float_as_uint(v.z) & 0x7FFFFFFFu) >> SSHIFT], 1u);
        atomicAdd(&sh[(__float_as_uint(v.w) & 0x7FFFFFFFu) >> SSHIFT], 1u);
    }
    __syncthreads();
    for (int i = threadIdx.x; i < SBINS; i += blockDim.x) {
        unsigned int c = sh[i];
        if (c) atomicAdd(&g_shist[i], c);
    }
}

// ---------------------------------------------------------------------------
// Locate the coarse bin of the estimated k-th value; open a 4-bin window.
__global__ void k_sscan() {
    __shared__ unsigned int suf[1024];
    int t = threadIdx.x;
    unsigned int s = 0;
#pragma unroll
    for (int j = 0; j < 8; j++) s += g_shist[t * 8 + j];
    suf[t] = s;
    __syncthreads();
    for (int d = 1; d < 1024; d <<= 1) {
        unsigned int v = (t + d < 1024) ? suf[t + d] : 0;
        __syncthreads();
        suf[t] += v;
        __syncthreads();
    }
    unsigned int segAbove = (t < 1023) ? suf[t + 1] : 0;
    if (suf[t] >= (unsigned)STARGET && segAbove < (unsigned)STARGET) {
        unsigned int acc = segAbove;
        int bin = t * 8;
        for (int j = 7; j >= 0; j--) {
            acc += g_shist[t * 8 + j];
            if (acc >= (unsigned)STARGET) { bin = t * 8 + j; break; }
        }
        int lo_bin = bin >= 2 ? bin - 2 : 0;
        if (lo_bin > SBINS - 4) lo_bin = SBINS - 4;
        g_lo = (unsigned)lo_bin << SSHIFT;
    }
}

// ---------------------------------------------------------------------------
// FUSED streaming pass = R2's k_count + R6's provisional write & ballot
// staging. Read x once, write provisional out (keep iff b>=hi), count
// 'above', atomically bin in-window elements into the exact 2^20 histogram
// (2.6% of elements, spread bins), stage window-touching f4 indices.
__global__ void __launch_bounds__(BLK_MAIN) k_main(const float4* __restrict__ x,
                                                   float4* __restrict__ out) {
    __shared__ unsigned s_stage[STAGE_CAP];
    __shared__ unsigned s_count, s_above, s_base;

    if (threadIdx.x == 0) { s_count = 0; s_above = 0; }
    __syncthreads();

    const unsigned lo = g_lo;
    const unsigned hi = lo + WIN_BINS;
    const unsigned lane = threadIdx.x & 31u;
    const unsigned stride = GRID_MAIN * BLK_MAIN;
    unsigned above = 0;

    // exactly 32 iterations per thread; warps always fully converged
    for (unsigned i = blockIdx.x * blockDim.x + threadIdx.x; i < (unsigned)N_VEC4;
         i += stride) {
        float4 v = x[i];
        unsigned b0 = __float_as_uint(v.x) & 0x7FFFFFFFu;
        unsigned b1 = __float_as_uint(v.y) & 0x7FFFFFFFu;
        unsigned b2 = __float_as_uint(v.z) & 0x7FFFFFFFu;
        unsigned b3 = __float_as_uint(v.w) & 0x7FFFFFFFu;
        float4 o;
        o.x = (b0 >= hi) ? v.x : 0.0f;
        o.y = (b1 >= hi) ? v.y : 0.0f;
        o.z = (b2 >= hi) ? v.z : 0.0f;
        o.w = (b3 >= hi) ? v.w : 0.0f;
        out[i] = o;
        above += (b0 >= hi) + (b1 >= hi) + (b2 >= hi) + (b3 >= hi);

        // unsigned wrap: b<lo -> huge -> false
        bool w0 = (b0 - lo) < WIN_BINS, w1 = (b1 - lo) < WIN_BINS;
        bool w2 = (b2 - lo) < WIN_BINS, w3 = (b3 - lo) < WIN_BINS;
        if (w0) atomicAdd(&g_winHist[b0 - lo], 1u);
        if (w1) atomicAdd(&g_winHist[b1 - lo], 1u);
        if (w2) atomicAdd(&g_winHist[b2 - lo], 1u);
        if (w3) atomicAdd(&g_winHist[b3 - lo], 1u);

        bool win = w0 | w1 | w2 | w3;
        unsigned m = __ballot_sync(0xFFFFFFFFu, win);
        if (m) {
            int leader = __ffs(m) - 1;
            unsigned base;
            if ((int)lane == leader)
                base = atomicAdd(&s_count, (unsigned)__popc(m));
            base = __shfl_sync(0xFFFFFFFFu, base, leader);
            if (win) {
                unsigned pos = base + __popc(m & ((1u << lane) - 1u));
                if (pos < STAGE_CAP) s_stage[pos] = i;
            }
        }
    }

#pragma unroll
    for (int off = 16; off; off >>= 1) above += __shfl_down_sync(0xFFFFFFFFu, above, off);
    if (lane == 0 && above) atomicAdd(&s_above, above);
    __syncthreads();

    if (threadIdx.x == 0) {
        if (s_above) atomicAdd(&g_above, s_above);
        unsigned n = s_count < STAGE_CAP ? s_count : STAGE_CAP;
        s_base = atomicAdd(&g_nList, n);
        s_count = n;
    }
    __syncthreads();
    unsigned n = s_count, base = s_base;
    for (unsigned j = threadIdx.x; j < n; j += BLK_MAIN) {
        unsigned pos = base + j;
        if (pos < LIST_CAP) g_i4List[pos] = s_stage[j];
    }
}

// ---------------------------------------------------------------------------
// Reduce the window histogram into 1024 chunk sums (one block per chunk).
__global__ void k_wreduce() {
    __shared__ unsigned int smr[256];
    unsigned int s = 0;
    int base = blockIdx.x * WCHUNK;
    for (int j = threadIdx.x; j < WCHUNK; j += 256) s += g_winHist[base + j];
    smr[threadIdx.x] = s;
    __syncthreads();
    for (int off = 128; off; off >>= 1) {
        if (threadIdx.x < off) smr[threadIdx.x] += smr[threadIdx.x + off];
        __syncthreads();
    }
    if (threadIdx.x == 0) g_chunkSum[blockIdx.x] = smr[0];
}

// ---------------------------------------------------------------------------
// Exact threshold T (31-bit key of k-th largest) + tie budget.
__global__ void k_wscan() {
    __shared__ unsigned int suf[1024];
    __shared__ int s_c;
    int t = threadIdx.x;

    suf[t] = g_chunkSum[t];
    __syncthreads();
    for (int d = 1; d < 1024; d <<= 1) {
        unsigned int v = (t + d < 1024) ? suf[t + d] : 0;
        __syncthreads();
        suf[t] += v;
        __syncthreads();
    }
    unsigned int above = g_above;
    long long kRem = (long long)K_TOP - (long long)above;
    unsigned int winTotal = suf[0];

    if (kRem < 1) {                    // degenerate: window missed low
        if (t == 0) { g_T = g_lo + WIN_BINS - 1; g_need = 0; }
        return;
    }
    if (kRem > (long long)winTotal) {  // degenerate: window missed high
        if (t == 0) { g_T = g_lo > 0 ? g_lo - 1 : 0; g_need = 0; }
        return;
    }
    unsigned int segAbove = (t < 1023) ? suf[t + 1] : 0;
    if ((long long)suf[t] >= kRem && (long long)segAbove < kRem) s_c = t;
    __syncthreads();
    int c = s_c;
    unsigned int baseAbove = (c < 1023) ? suf[c + 1] : 0;
    __syncthreads();

    suf[t] = g_winHist[c * WCHUNK + t];
    __syncthreads();
    for (int d = 1; d < 1024; d <<= 1) {
        unsigned int v = (t + d < 1024) ? suf[t + d] : 0;
        __syncthreads();
        suf[t] += v;
        __syncthreads();
    }
    unsigned int binAbove = baseAbove + ((t < 1023) ? suf[t + 1] : 0);
    if ((long long)(baseAbove + suf[t]) >= kRem && (long long)binAbove < kRem) {
        unsigned int bin = (unsigned)c * WCHUNK + (unsigned)t;
        g_T = g_lo + bin;
        g_need = (unsigned)(kRem - (long long)binAbove);
    }
}

// ---------------------------------------------------------------------------
// Fix-up over the staged list only (no full re-stream): gather each staged
// float4, write components with b > T, collect exact ties (b == T).
__global__ void k_fix(const float4* __restrict__ x, float* __restrict__ out) {
    unsigned n = g_nList; if (n > LIST_CAP) n = LIST_CAP;
    unsigned lo = g_lo, T = g_T;
    int tid = blockIdx.x * blockDim.x + threadIdx.x;
    int stride = gridDim.x * blockDim.x;
    for (unsigned j = tid; j < n; j += stride) {
        unsigned i4 = g_i4List[j];
        float4 v = x[i4];
        unsigned raw[4] = { __float_as_uint(v.x), __float_as_uint(v.y),
                            __float_as_uint(v.z), __float_as_uint(v.w) };
#pragma unroll
        for (int c = 0; c < 4; c++) {
            unsigned b = raw[c] & 0x7FFFFFFFu;
            if ((b - lo) < WIN_BINS) {
                if (b > T) {
                    out[i4 * 4u + c] = __uint_as_float(raw[c]);
                } else if (b == T) {
                    unsigned p = atomicAdd(&g_eqCount, 1u);
                    if (p < EQ_CAP) g_eq[p] = make_uint2(i4 * 4u + c, raw[c]);
                }
            }
        }
    }
}

// ---------------------------------------------------------------------------
// Ties at exactly T: keep the `need` smallest flat indices (lax.top_k order).
__global__ void k_tie(float* __restrict__ out) {
    unsigned int cnt = g_eqCount;
    if (cnt > EQ_CAP) cnt = EQ_CAP;
    unsigned int need = g_need;
    if (need == 0 || cnt == 0) return;
    if (need >= cnt) {
        for (unsigned i = threadIdx.x; i < cnt; i += blockDim.x)
            out[g_eq[i].x] = __uint_as_float(g_eq[i].y);
        return;
    }
    for (unsigned i = threadIdx.x; i < cnt; i += blockDim.x) {
        uint2 ei = g_eq[i];
        unsigned r = 0;
        for (unsigned j = 0; j < cnt; j++) r += (g_eq[j].x < ei.x) ? 1u : 0u;
        if (r < need) out[ei.x] = __uint_as_float(ei.y);
    }
}

// ---------------------------------------------------------------------------
extern "C" void kernel_launch(void* const* d_in, const int* in_sizes, int n_in,
                              void* d_out, int out_size) {
    const float* x = (const float*)d_in[0];
    float* out = (float*)d_out;

    k_zero<<<512, 256>>>();
    k_sample<<<128, 256>>>((const float4*)x);
    k_sscan<<<1, 1024>>>();
    k_main<<<GRID_MAIN, BLK_MAIN>>>((const float4*)x, (float4*)out);
    k_wreduce<<<NCHUNKS, 256>>>();
    k_wscan<<<1, 1024>>>();
    k_fix<<<256, 256>>>((const float4*)x, out);
    k_tie<<<1, 256>>>(out);
}